// round 16
// baseline (speedup 1.0000x reference)
#include <cuda_runtime.h>
#include <cstdint>

// Centroids argmin via legacy mma.sync 3xTF32 split (fp32-grade accuracy).
// score[n,c] = |c|^2 - 2*(latent[n].coords[c]);  out[n] = argmin_c (float)
// R16: FRAGMENT-MAJOR smem layouts. A and B stored pre-permuted in exact
// m16n8k8 fragment order: per k-step a warp issues 4x LDS.128 (A) +
// 8x LDS.64 (B) instead of 32 scalar LDS.32. Pads (A:132, B:66 floats per
// ks-block) keep both the scatter-STS commits and fragment loads conflict-free.
// CTA: 128 rows x 64 cents, 8 warps (4M x 2N), warp tile 32x32, K=128.

#define DIM      128
#define CTA_M    128
#define TILE_N   64
#define THREADS  256

// Fragment-major A: [wm(4)][mf(2)][ks(16)][lane(32)*4 regs + 4 pad] = 132/ks
#define A_KS_STRIDE 132
#define A_FRAG(wm_mf, ks) (((wm_mf) * 16 + (ks)) * A_KS_STRIDE)
#define SA_HIP 0
#define SA_LOP (8 * 16 * A_KS_STRIDE)             // 16896
// Fragment-major B: [wn(2)][nf(4)][ks(16)][lane(32)*2 regs + 2 pad] = 66/ks
#define B_KS_STRIDE 66
#define B_FRAG(wn_nf, ks) (((wn_nf) * 16 + (ks)) * B_KS_STRIDE)
#define SB_HIP (2 * SA_LOP)                       // 33792
#define SB_LOP (SB_HIP + 8 * 16 * B_KS_STRIDE)    // 42240
#define S_C2   (SB_LOP + 8 * 16 * B_KS_STRIDE)    // 50688
#define SMEM_FLOATS (S_C2 + TILE_N)               // 50752 (~203KB)

__device__ float g_c2[2048];
__device__ float g_bhi[2048 * DIM];     // coords tf32-hi (1 MB)
__device__ float g_blo[2048 * DIM];     // coords tf32-lo (1 MB)

__device__ __forceinline__ uint32_t tf32_rna(float x) {
    uint32_t u;
    asm("cvt.rna.tf32.f32 %0, %1;" : "=r"(u) : "f"(x));
    return u;
}
__device__ __forceinline__ void tf32_split(float x, float& hi, float& lo) {
    uint32_t h = tf32_rna(x);
    hi = __uint_as_float(h);
    lo = __uint_as_float(tf32_rna(x - hi));
}
__device__ __forceinline__ void mma_tf32(float* c, const uint4& a,
                                         const float2& b) {
    asm volatile(
        "mma.sync.aligned.m16n8k8.row.col.f32.tf32.tf32.f32 "
        "{%0,%1,%2,%3}, {%4,%5,%6,%7}, {%8,%9}, {%0,%1,%2,%3};"
        : "+f"(c[0]), "+f"(c[1]), "+f"(c[2]), "+f"(c[3])
        : "r"(a.x), "r"(a.y), "r"(a.z), "r"(a.w),
          "r"(__float_as_uint(b.x)), "r"(__float_as_uint(b.y)));
}

// ---- prep: per-centroid |c|^2 + tf32 hi/lo split (warp per centroid) ----
__global__ void prep_kernel(const float* __restrict__ coords, int n_cent) {
    int c    = blockIdx.x * 8 + (threadIdx.x >> 5);
    int lane = threadIdx.x & 31;
    if (c >= n_cent) return;
    const float4* p = reinterpret_cast<const float4*>(coords + (size_t)c * DIM);
    float4 v = p[lane];
    float s = v.x * v.x + v.y * v.y + v.z * v.z + v.w * v.w;
    #pragma unroll
    for (int off = 16; off > 0; off >>= 1)
        s += __shfl_xor_sync(0xffffffffu, s, off);
    if (lane == 0) g_c2[c] = s;

    float4 hi, lo;
    tf32_split(v.x, hi.x, lo.x);
    tf32_split(v.y, hi.y, lo.y);
    tf32_split(v.z, hi.z, lo.z);
    tf32_split(v.w, hi.w, lo.w);
    reinterpret_cast<float4*>(g_bhi + (size_t)c * DIM)[lane] = hi;
    reinterpret_cast<float4*>(g_blo + (size_t)c * DIM)[lane] = lo;
}

// Scatter one float4 (row r, kq) into fragment-major A layout.
__device__ __forceinline__ void scatterA(float* base, int r, int kq,
                                         const float4& v) {
    int wm = r >> 5, rr = r & 31;
    int mf = rr >> 4, fr = rr & 15;
    int rs = fr >> 3, g = fr & 7;
    int ks = kq >> 1, kh = kq & 1;
    int q  = rs + 2 * kh;
    float* p = base + A_FRAG(wm * 2 + mf, ks) + q;
    p[(g * 4 + 0) * 4] = v.x;
    p[(g * 4 + 1) * 4] = v.y;
    p[(g * 4 + 2) * 4] = v.z;
    p[(g * 4 + 3) * 4] = v.w;
}
// Scatter one float4 (col c, kq) into fragment-major B layout.
__device__ __forceinline__ void scatterB(float* base, int c, int kq,
                                         const float4& v) {
    int wn = c >> 5, cc = c & 31;
    int nf = cc >> 3, g = cc & 7;
    int ks = kq >> 1, kh = kq & 1;
    float* p = base + B_FRAG(wn * 4 + nf, ks) + kh;
    p[(g * 4 + 0) * 2] = v.x;
    p[(g * 4 + 1) * 2] = v.y;
    p[(g * 4 + 2) * 2] = v.z;
    p[(g * 4 + 3) * 2] = v.w;
}

// ---- main: 3xTF32 mma GEMM + running argmin ----
__global__ void __launch_bounds__(THREADS, 1)
centroids_mma_kernel(const float* __restrict__ latent,
                     float* __restrict__ out,
                     int n_rows, int n_cent)
{
    extern __shared__ float sm[];

    const int tid   = threadIdx.x;
    const int lane  = tid & 31;
    const int w     = tid >> 5;
    const int warpM = w >> 1;            // 0..3
    const int warpN = w & 1;             // 0..1
    const int g     = lane >> 2;         // group 0..7
    const int t     = lane & 3;          // thread-in-group 0..3
    const int rowBase = blockIdx.x * CTA_M;
    const int n_tiles = n_cent / TILE_N;

    // ---- A tile: load + split + scatter to fragment-major ----
    {
        const float4* g4 = reinterpret_cast<const float4*>(latent);
        for (int it = tid; it < CTA_M * 32; it += THREADS) {
            int r  = it >> 5;
            int kq = it & 31;
            int gr = rowBase + r; if (gr >= n_rows) gr = n_rows - 1;
            float4 v = g4[(size_t)gr * 32 + kq];
            float4 hi, lo;
            tf32_split(v.x, hi.x, lo.x);
            tf32_split(v.y, hi.y, lo.y);
            tf32_split(v.z, hi.z, lo.z);
            tf32_split(v.w, hi.w, lo.w);
            scatterA(sm + SA_HIP, r, kq, hi);
            scatterA(sm + SA_LOP, r, kq, lo);
        }
    }
    // ---- B tile 0 -> fragment-major ----
    {
        const float4* bh = reinterpret_cast<const float4*>(g_bhi);
        const float4* bl = reinterpret_cast<const float4*>(g_blo);
        for (int it = tid; it < TILE_N * 32; it += THREADS) {
            int r  = it >> 5;
            int kq = it & 31;
            scatterB(sm + SB_HIP, r, kq, bh[(size_t)r * 32 + kq]);
            scatterB(sm + SB_LOP, r, kq, bl[(size_t)r * 32 + kq]);
        }
        if (tid < TILE_N) sm[S_C2 + tid] = g_c2[tid];
    }
    __syncthreads();

    float best[2][2];
    int   bidx[2][2];
    #pragma unroll
    for (int mf = 0; mf < 2; mf++)
        #pragma unroll
        for (int rs = 0; rs < 2; rs++) { best[mf][rs] = 3.402823466e38f; bidx[mf][rs] = 0; }

    const int pfR = tid >> 5;            // prefetch base row (0..7)
    const int pfK = tid & 31;            // prefetch kq slot

    const float4* bh4 = reinterpret_cast<const float4*>(g_bhi);
    const float4* bl4 = reinterpret_cast<const float4*>(g_blo);

    for (int nb = 0; nb < n_tiles; nb++) {
        // ---- prefetch next B tile into registers ----
        float4 pf_hi[8], pf_lo[8];
        float  pf_c2 = 0.0f;
        if (nb + 1 < n_tiles) {
            #pragma unroll
            for (int p = 0; p < 8; p++) {
                size_t src = (size_t)((nb + 1) * TILE_N + pfR + p * 8) * 32 + pfK;
                pf_hi[p] = bh4[src];
                pf_lo[p] = bl4[src];
            }
            if (tid < TILE_N) pf_c2 = g_c2[(nb + 1) * TILE_N + tid];
        }

        // ---- compute current tile: 3 independent accumulator banks ----
        float acc[3][2][4][4];
        #pragma unroll
        for (int s = 0; s < 3; s++)
            #pragma unroll
            for (int mf = 0; mf < 2; mf++)
                #pragma unroll
                for (int nf = 0; nf < 4; nf++)
                    #pragma unroll
                    for (int q = 0; q < 4; q++) acc[s][mf][nf][q] = 0.0f;

        #pragma unroll 2
        for (int ks = 0; ks < 16; ks++) {
            uint4  ahi[2], alo[2];
            float2 bhi[4], blo[4];
            #pragma unroll
            for (int mf = 0; mf < 2; mf++) {
                int ab = A_FRAG(warpM * 2 + mf, ks) + lane * 4;
                ahi[mf] = *reinterpret_cast<const uint4*>(sm + SA_HIP + ab);
                alo[mf] = *reinterpret_cast<const uint4*>(sm + SA_LOP + ab);
            }
            #pragma unroll
            for (int nf = 0; nf < 4; nf++) {
                int bb = B_FRAG(warpN * 4 + nf, ks) + lane * 2;
                bhi[nf] = *reinterpret_cast<const float2*>(sm + SB_HIP + bb);
                blo[nf] = *reinterpret_cast<const float2*>(sm + SB_LOP + bb);
            }
            #pragma unroll
            for (int mf = 0; mf < 2; mf++)
                #pragma unroll
                for (int nf = 0; nf < 4; nf++)
                    mma_tf32(acc[0][mf][nf], ahi[mf], bhi[nf]);
            #pragma unroll
            for (int mf = 0; mf < 2; mf++)
                #pragma unroll
                for (int nf = 0; nf < 4; nf++)
                    mma_tf32(acc[1][mf][nf], ahi[mf], blo[nf]);
            #pragma unroll
            for (int mf = 0; mf < 2; mf++)
                #pragma unroll
                for (int nf = 0; nf < 4; nf++)
                    mma_tf32(acc[2][mf][nf], alo[mf], bhi[nf]);
        }

        // ---- tile epilogue: fold banks, scores, running argmin ----
        #pragma unroll
        for (int nf = 0; nf < 4; nf++) {
            int cl = warpN * 32 + nf * 8 + 2 * t;
            float2 cc = *reinterpret_cast<const float2*>(sm + S_C2 + cl);
            int c0 = nb * TILE_N + cl;
            #pragma unroll
            for (int mf = 0; mf < 2; mf++) {
                float d0 = acc[0][mf][nf][0] + acc[1][mf][nf][0] + acc[2][mf][nf][0];
                float d1 = acc[0][mf][nf][1] + acc[1][mf][nf][1] + acc[2][mf][nf][1];
                float d2 = acc[0][mf][nf][2] + acc[1][mf][nf][2] + acc[2][mf][nf][2];
                float d3 = acc[0][mf][nf][3] + acc[1][mf][nf][3] + acc[2][mf][nf][3];
                float s0 = fmaf(-2.0f, d0, cc.x);
                float s1 = fmaf(-2.0f, d1, cc.y);
                float s2 = fmaf(-2.0f, d2, cc.x);
                float s3 = fmaf(-2.0f, d3, cc.y);
                if (s0 < best[mf][0]) { best[mf][0] = s0; bidx[mf][0] = c0; }
                if (s1 < best[mf][0]) { best[mf][0] = s1; bidx[mf][0] = c0 + 1; }
                if (s2 < best[mf][1]) { best[mf][1] = s2; bidx[mf][1] = c0; }
                if (s3 < best[mf][1]) { best[mf][1] = s3; bidx[mf][1] = c0 + 1; }
            }
        }

        __syncthreads();   // all reads of tile nb complete

        // ---- commit prefetched B tile (scatter to fragment-major) ----
        if (nb + 1 < n_tiles) {
            #pragma unroll
            for (int p = 0; p < 8; p++) {
                int r = pfR + p * 8;
                scatterB(sm + SB_HIP, r, pfK, pf_hi[p]);
                scatterB(sm + SB_LOP, r, pfK, pf_lo[p]);
            }
            if (tid < TILE_N) sm[S_C2 + tid] = pf_c2;
            __syncthreads();
        }
    }

    // ---- reduce across the 4 t-lanes of each group ----
    #pragma unroll
    for (int mf = 0; mf < 2; mf++)
        #pragma unroll
        for (int rs = 0; rs < 2; rs++) {
            float s = best[mf][rs];
            int   i = bidx[mf][rs];
            #pragma unroll
            for (int off = 1; off <= 2; off <<= 1) {
                float os = __shfl_xor_sync(0xffffffffu, s, off);
                int   oi = __shfl_xor_sync(0xffffffffu, i, off);
                if (os < s || (os == s && oi < i)) { s = os; i = oi; }
            }
            best[mf][rs] = s;
            bidx[mf][rs] = i;
        }

    // ---- cross-warpN reduction via smem ----
    __syncthreads();
    float2* red = reinterpret_cast<float2*>(sm);   // [CTA_M][2]
    if (t == 0) {
        #pragma unroll
        for (int mf = 0; mf < 2; mf++)
            #pragma unroll
            for (int rs = 0; rs < 2; rs++) {
                int rl = warpM * 32 + mf * 16 + rs * 8 + g;
                red[rl * 2 + warpN] =
                    make_float2(best[mf][rs], __int_as_float(bidx[mf][rs]));
            }
    }
    __syncthreads();
    if (tid < CTA_M) {
        float2 p0 = red[tid * 2 + 0];
        float2 p1 = red[tid * 2 + 1];
        int   i0 = __float_as_int(p0.y);
        int   i1 = __float_as_int(p1.y);
        int   bi = (p1.x < p0.x || (p1.x == p0.x && i1 < i0)) ? i1 : i0;
        int row = rowBase + tid;
        if (row < n_rows) out[row] = (float)bi;
    }
}

extern "C" void kernel_launch(void* const* d_in, const int* in_sizes, int n_in,
                              void* d_out, int out_size)
{
    // Inputs by size: latent (131072x128) larger than coords (2048x128).
    int i_lat = 0, i_crd = 1;
    if (n_in >= 2 && in_sizes[1] > in_sizes[0]) { i_lat = 1; i_crd = 0; }

    const float* latent = (const float*)d_in[i_lat];
    const float* coords = (const float*)d_in[i_crd];

    int n_rows_a = out_size;
    int n_rows_b = in_sizes[i_lat] / DIM;
    int n_rows = n_rows_a < n_rows_b ? n_rows_a : n_rows_b;
    int n_cent = in_sizes[i_crd] / DIM;       // 2048
    float* out = (float*)d_out;

    size_t smem = SMEM_FLOATS * sizeof(float);   // ~203 KB

    static bool attr_set = false;
    if (!attr_set) {
        cudaFuncSetAttribute(centroids_mma_kernel,
                             cudaFuncAttributeMaxDynamicSharedMemorySize,
                             (int)smem);
        attr_set = true;
    }

    prep_kernel<<<(n_cent + 7) / 8, 256>>>(coords, n_cent);

    dim3 grid((n_rows + CTA_M - 1) / CTA_M);
    centroids_mma_kernel<<<grid, THREADS, smem>>>(latent, out, n_rows, n_cent);
}